// round 17
// baseline (speedup 1.0000x reference)
#include <cuda_runtime.h>
#include <cuda_bf16.h>
#include <math_constants.h>
#include <cstdint>

#define B_  4
#define L_  4096
#define D_  256
#define BL_ (B_ * L_)
#define NSPLIT 8
#define KEYS_PER_SPLIT (L_ / NSPLIT)            /* 512 */
#define TILES_PER_SPLIT (KEYS_PER_SPLIT / 128)  /* 4 */
#define CHUNKS2 (TILES_PER_SPLIT * 4)           /* 16 x 64-d chunks */

// g_Q / g_KB: PLAIN row-major bf16 (ldmatrix layout).
__device__ __align__(1024) __nv_bfloat16 g_Q[BL_ * D_];
__device__ __align__(1024) __nv_bfloat16 g_KB[BL_ * D_];
__device__ __align__(1024) float4 g_part[NSPLIT][BL_];   // (l, ax, ay)
__device__ int g_cnt[B_ * 32];                           // merge counters

// ---------------------------------------------------------------------------
// helpers
// ---------------------------------------------------------------------------
__device__ __forceinline__ uint32_t smem_u32(const void* p) {
    uint32_t a;
    asm("{ .reg .u64 t; cvta.to.shared.u64 t, %1; cvt.u32.u64 %0, t; }"
        : "=r"(a) : "l"(p));
    return a;
}

__device__ __forceinline__ float ex2f(float x) {
    float y;
    asm("ex2.approx.f32 %0, %1;" : "=f"(y) : "f"(x));
    return y;
}

__device__ __forceinline__ void cp16(uint32_t dst, const void* src) {
    asm volatile("cp.async.cg.shared.global [%0], [%1], 16;"
                 :: "r"(dst), "l"(src) : "memory");
}
__device__ __forceinline__ void cp_commit() {
    asm volatile("cp.async.commit_group;" ::: "memory");
}
__device__ __forceinline__ void cp_wait0() {
    asm volatile("cp.async.wait_group 0;" ::: "memory");
}

__device__ __forceinline__ void sts128(uint32_t a, uint32_t r0, uint32_t r1,
                                       uint32_t r2, uint32_t r3) {
    asm volatile("st.shared.v4.b32 [%0], {%1, %2, %3, %4};"
                 :: "r"(a), "r"(r0), "r"(r1), "r"(r2), "r"(r3) : "memory");
}

#define LDSM_X4(r0, r1, r2, r3, addr) \
    asm volatile("ldmatrix.sync.aligned.m8n8.x4.shared.b16 " \
                 "{%0, %1, %2, %3}, [%4];" \
                 : "=r"(r0), "=r"(r1), "=r"(r2), "=r"(r3) : "r"(addr))

#define LDSM_X2_TRANS(r0, r1, addr) \
    asm volatile("ldmatrix.sync.aligned.m8n8.x2.trans.shared.b16 " \
                 "{%0, %1}, [%2];" \
                 : "=r"(r0), "=r"(r1) : "r"(addr))

#define MMA_BF16(d, a0, a1, a2, a3, b0, b1) \
    asm volatile("mma.sync.aligned.m16n8k16.row.col.f32.bf16.bf16.f32 " \
                 "{%0,%1,%2,%3},{%4,%5,%6,%7},{%8,%9},{%0,%1,%2,%3};" \
                 : "+f"((d)[0]), "+f"((d)[1]), "+f"((d)[2]), "+f"((d)[3]) \
                 : "r"(a0), "r"(a1), "r"(a2), "r"(a3), "r"(b0), "r"(b1))

__device__ __forceinline__ uint32_t bf2(float lo, float hi) {
    __nv_bfloat162 v = __floats2bfloat162_rn(lo, hi);
    return *(uint32_t*)&v;
}

// ---------------------------------------------------------------------------
// Kernel 1: proj via mma.sync bf16 + ldmatrix. One CTA = 128 rows x BOTH
// Wq and Wk; zeros its merge counter. W streamed as 8 x 64-d FP32 chunks
// (4 Wq + 4 Wk) via cp.async into a single staging buffer, converted
// in-SMEM to bf16 double-buffered slots (identical _rn rounding to the old
// convert kernel). X read fp32 from latents (LDG -> bf16 pack -> STS).
// Row L2-norm fused; output PLAIN row-major to g_Q / g_KB.
// 512 threads = 16 warps (warpm 0..3 x warpn 0..3), warp tile 32m x 64n.
// ---------------------------------------------------------------------------
#define PXST 528                             /* X row bytes (512 + 16) */
#define PWST2 144                            /* bf16 W row bytes (128 + 16) */
#define PFST 272                             /* fp32 W row bytes (256 + 16) */
#define P_SLOT (D_ * PWST2)                  /* 36864 */
#define P_SMX 0
#define P_SMW (128 * PXST)                   /* 67584 */
#define P_SMF (P_SMW + 2 * P_SLOT)           /* 141312, fp32 staging 69632 */
#define P_RED (P_SMF + D_ * PFST)            /* 210944 */
#define P_TOT (P_RED + 2048)                 /* 212992 */

__global__ void __launch_bounds__(512, 1)
proj_mma_kernel(const float* __restrict__ latents,
                const float* __restrict__ Wq, const float* __restrict__ Wk) {
    extern __shared__ __align__(1024) char smem[];
    const uint32_t sb = smem_u32(smem);
    const int tid  = threadIdx.x;
    const int lane = tid & 31;
    const int warp = tid >> 5;
    const int warpm = warp & 3, warpn = warp >> 2;   // 4 x 4
    const int g  = lane >> 2, t4 = lane & 3;
    const int row0 = blockIdx.x * 128;

    if (tid == 0) g_cnt[blockIdx.x] = 0;    // 128 CTAs == 128 counters

    // ldmatrix lane-address bases (same scheme as attn).
    const uint32_t qlm = sb + P_SMX +
        (warpm * 32 + (lane & 15)) * PXST + (lane >> 4) * 16;
    const uint32_t klm =
        (warpn * 64 + ((lane >> 4) << 3) + (lane & 7)) * PWST2 +
        ((lane >> 3) & 1) * 16;

    // fp32 W-chunk cp.async offsets: 4096 cp16 per chunk, 8 per thread.
    uint32_t fdst[8];
    int fsrc[8];
#pragma unroll
    for (int i = 0; i < 8; i++) {
        int seg = tid + 512 * i;            // 0..4095; 16 x 16B per W row
        int wr = seg >> 4, wo = seg & 15;
        fdst[i] = wr * PFST + wo * 16;
        fsrc[i] = wr * D_ + wo * 4;         // floats within chunk d-window
    }

    // ---- prologue: fp32 W chunk 0 (async) + X fp32->bf16 plain STS ----
#pragma unroll
    for (int i = 0; i < 8; i++)
        cp16(sb + P_SMF + fdst[i], Wq + fsrc[i]);
    cp_commit();
    {
        const float4* __restrict__ Xf4 =
            (const float4*)(latents + (size_t)row0 * D_);
#pragma unroll
        for (int i = 0; i < 4; i++) {
            int idx = tid + 512 * i;            // 0..2047
            int r = idx >> 4, gg = idx & 15;    // row, 16-d group
            const float4* p = Xf4 + r * 64 + gg * 4;
            float4 v0 = __ldg(p + 0), v1 = __ldg(p + 1);
            float4 v2 = __ldg(p + 2), v3 = __ldg(p + 3);
            uint32_t sa = sb + P_SMX + r * PXST + gg * 32;
            sts128(sa,      bf2(v0.x, v0.y), bf2(v0.z, v0.w),
                            bf2(v1.x, v1.y), bf2(v1.z, v1.w));
            sts128(sa + 16, bf2(v2.x, v2.y), bf2(v2.z, v2.w),
                            bf2(v3.x, v3.y), bf2(v3.z, v3.w));
        }
    }

    // Conversion assignment: thread = (row, half-row of 32 d).
    const int cvr = tid >> 1, cvh = tid & 1;
    const char* fbase = smem + P_SMF + cvr * PFST + cvh * 128;
    const uint32_t bbase = cvr * PWST2 + cvh * 64;

    float* __restrict__ red = (float*)(smem + P_RED);

    for (int which = 0; which < 2; which++) {
        float S[2][8][4];
#pragma unroll
        for (int mt = 0; mt < 2; mt++)
#pragma unroll
            for (int nb = 0; nb < 8; nb++)
#pragma unroll
                for (int r = 0; r < 4; r++) S[mt][nb][r] = 0.f;

        for (int c2 = 0; c2 < 4; c2++) {
            const int gc = which * 4 + c2;
            cp_wait0();                     // fp32 chunk gc landed
            __syncthreads();                // + bf16 slot gc&1 free (2 ago)
            // Convert fp32 staging -> bf16 slot gc&1 (same _rn rounding).
            {
                const uint32_t bslot = sb + P_SMW + (gc & 1) * P_SLOT + bbase;
#pragma unroll
                for (int j = 0; j < 2; j++) {
                    const float4* f = (const float4*)(fbase + j * 64);
                    float4 v0 = f[0], v1 = f[1], v2 = f[2], v3 = f[3];
                    sts128(bslot + j * 32,
                           bf2(v0.x, v0.y), bf2(v0.z, v0.w),
                           bf2(v1.x, v1.y), bf2(v1.z, v1.w));
                    sts128(bslot + j * 32 + 16,
                           bf2(v2.x, v2.y), bf2(v2.z, v2.w),
                           bf2(v3.x, v3.y), bf2(v3.z, v3.w));
                }
            }
            __syncthreads();                // bf16 ready + fp32 staging free
            if (gc + 1 < 8) {
                int nc = gc + 1;
                const float* src = (nc < 4 ? Wq : Wk) + (nc & 3) * 64;
#pragma unroll
                for (int i = 0; i < 8; i++)
                    cp16(sb + P_SMF + fdst[i], src + fsrc[i]);
                cp_commit();
            }

            const uint32_t slot = sb + P_SMW + (gc & 1) * P_SLOT;
#pragma unroll
            for (int ks = 0; ks < 4; ks++) {
                const int kbase_a = c2 * 128 + ks * 32;  // X: full-d rows
                const int kbase_b = ks * 32;             // W slot: 64-d rows
                uint32_t a[2][4];
                LDSM_X4(a[0][0], a[0][1], a[0][2], a[0][3], qlm + kbase_a);
                LDSM_X4(a[1][0], a[1][1], a[1][2], a[1][3],
                        qlm + 16 * PXST + kbase_a);
#pragma unroll
                for (int nbp = 0; nbp < 4; nbp++) {
                    uint32_t b0, b1, c0, c1;
                    LDSM_X4(b0, b1, c0, c1,
                            slot + klm + nbp * 16 * PWST2 + kbase_b);
                    MMA_BF16(S[0][2 * nbp],     a[0][0], a[0][1], a[0][2],
                             a[0][3], b0, b1);
                    MMA_BF16(S[0][2 * nbp + 1], a[0][0], a[0][1], a[0][2],
                             a[0][3], c0, c1);
                    MMA_BF16(S[1][2 * nbp],     a[1][0], a[1][1], a[1][2],
                             a[1][3], b0, b1);
                    MMA_BF16(S[1][2 * nbp + 1], a[1][0], a[1][1], a[1][2],
                             a[1][3], c0, c1);
                }
            }
        }

        // ---- row sum-of-squares: quad shfl + cross-warpn exchange ----
        __syncthreads();   // last chunk's loads done before red reuse below
#pragma unroll
        for (int mt = 0; mt < 2; mt++)
#pragma unroll
            for (int h = 0; h < 2; h++) {
                float v = 0.f;
#pragma unroll
                for (int nb = 0; nb < 8; nb++) {
                    v = fmaf(S[mt][nb][2 * h], S[mt][nb][2 * h], v);
                    v = fmaf(S[mt][nb][2 * h + 1], S[mt][nb][2 * h + 1], v);
                }
                v += __shfl_xor_sync(0xffffffffu, v, 1);
                v += __shfl_xor_sync(0xffffffffu, v, 2);
                if (t4 == 0)
                    red[warpn * 128 + warpm * 32 + mt * 16 + h * 8 + g] = v;
            }
        __syncthreads();

        // PLAIN row-major output: S[mt][nb] covers cols warpn*64+nb*8+2t4(+1)
        // -> pair index j = warpn*32 + nb*4 + t4.
        __nv_bfloat162* __restrict__ Out =
            (__nv_bfloat162*)(which ? g_KB : g_Q);
#pragma unroll
        for (int mt = 0; mt < 2; mt++)
#pragma unroll
            for (int h = 0; h < 2; h++) {
                int rowl = warpm * 32 + mt * 16 + h * 8 + g;
                float tot = (red[rowl] + red[128 + rowl]) +
                            (red[256 + rowl] + red[384 + rowl]);
                float scale = 1.0f / fmaxf(sqrtf(tot), 1e-12f);
                __nv_bfloat162* orow = Out + (size_t)(row0 + rowl) * 128;
#pragma unroll
                for (int nb = 0; nb < 8; nb++) {
                    int j = warpn * 32 + nb * 4 + t4;
                    orow[j] = __floats2bfloat162_rn(
                        S[mt][nb][2 * h] * scale, S[mt][nb][2 * h + 1] * scale);
                }
            }
        __syncthreads();   // red reads done before next pass writes
    }
}

// ---------------------------------------------------------------------------
// Kernel 2: flash attention partials + fused finalize (last CTA merges).
// Grid (32 qtiles, B, NSPLIT=8); 2 CTAs co-resident per SM.
// QK fragments via ldmatrix.x4; PV contraction on the tensor pipe
// (S C-frag == A-frag identity; V = [x, y, 1, 0..] via ldmatrix.x2.trans).
// V for the whole split staged ONCE in the prologue (8 KB).
// ---------------------------------------------------------------------------
#define QST   528
#define KST2  144                            /* 128B data + 16 pad */
#define SLOT2 (128 * KST2)                   /* 18432 */
#define SM_Q   0
#define SM_K   (128 * QST)                   /* 67584 */
#define SM_V   (SM_K + 2 * SLOT2)            /* 104448 */
#define SM_R   SM_K                          /* overlay on dead K slots */
#define SM_TOT (SM_V + KEYS_PER_SPLIT * 16)  /* 112640 */

#define SCALE_EX2 14.4269504088896340f       /* 10 * log2(e) */

__global__ void __launch_bounds__(256, 2)
attn_kernel(const float* __restrict__ coords,
            const float* __restrict__ alpha_p,
            float* __restrict__ out_new,
            float* __restrict__ out_disp) {
    extern __shared__ __align__(1024) char smem[];
    __shared__ int s_last;
    const uint32_t sb = smem_u32(smem);
    const int tid  = threadIdx.x;
    const int lane = tid & 31;
    const int warp = tid >> 5;
    const int warpm = warp & 3, warpn = warp >> 2;
    const int g  = lane >> 2, t4 = lane & 3;
    const int b  = blockIdx.y;
    const int q0 = blockIdx.x * 128;
    const int split = blockIdx.z;

    const __nv_bfloat16* __restrict__ Qg = g_Q + (size_t)(b * L_ + q0) * D_;
    const __nv_bfloat16* __restrict__ KgT =
        g_KB + (size_t)(b * L_ + split * KEYS_PER_SPLIT) * D_;
    const float2* __restrict__ Cg2 = (const float2*)coords + (size_t)b * L_ +
                                     split * KEYS_PER_SPLIT;

    // ldmatrix lane-address bases.
    const uint32_t qlm = sb + SM_Q +
        (warpm * 32 + (lane & 15)) * QST + (lane >> 4) * 16;
    const uint32_t klm =
        (warpn * 64 + ((lane >> 4) << 3) + (lane & 7)) * KST2 +
        ((lane >> 3) & 1) * 16;
    // V rows (16B each): lanes 0-15 supply key-row addresses.
    const uint32_t vlm = sb + SM_V + (warpn * 64 + (lane & 15)) * 16;

    // K-chunk cp.async offsets: 1024 cp16 per 64-d chunk, 4 per thread.
    uint32_t kdst[4];
    int ksrc[4];
#pragma unroll
    for (int i = 0; i < 4; i++) {
        int seg = tid + 256 * i;            // 0..1023; 8 x 16B per key row
        int kr = seg >> 3, ko = (seg & 7) * 16;
        kdst[i] = kr * KST2 + ko;
        ksrc[i] = kr * D_ + ko / 2;         // elements within chunk d-window
    }

    // ---- prologue: Q tile (async) + V staging (all 512 keys) + chunk 0 ----
#pragma unroll
    for (int i = 0; i < 16; i++) {
        int seg = tid + 256 * i;
        int row = seg >> 5, o = seg & 31;
        cp16(sb + SM_Q + row * QST + o * 16, Qg + row * D_ + o * 8);
    }
    cp_commit();
#pragma unroll
    for (int i = 0; i < 2; i++) {
        int row = tid + 256 * i;
        float2 cc = Cg2[row];
        sts128(sb + SM_V + row * 16, bf2(cc.x, cc.y), 0x00003F80u, 0u, 0u);
    }
#pragma unroll
    for (int i = 0; i < 4; i++)
        cp16(sb + SM_K + kdst[i], KgT + ksrc[i]);
    cp_commit();

    float O[2][4];
#pragma unroll
    for (int mt = 0; mt < 2; mt++)
#pragma unroll
        for (int r = 0; r < 4; r++) O[mt][r] = 0.f;

    for (int t = 0; t < TILES_PER_SPLIT; t++) {
        float S[2][8][4];
#pragma unroll
        for (int mt = 0; mt < 2; mt++)
#pragma unroll
            for (int nb = 0; nb < 8; nb++)
#pragma unroll
                for (int r = 0; r < 4; r++) S[mt][nb][r] = 0.f;

        for (int c4 = 0; c4 < 4; c4++) {
            const int c = t * 4 + c4;
            cp_wait0();                     // chunk c landed
            __syncthreads();                // all warps done with chunk c-1
            if (c + 1 < CHUNKS2) {
                int nc = c + 1;
                uint32_t slot = sb + SM_K + (nc & 1) * SLOT2;
                const __nv_bfloat16* src =
                    KgT + (nc >> 2) * (128 * D_) + (nc & 3) * 64;
#pragma unroll
                for (int i = 0; i < 4; i++)
                    cp16(slot + kdst[i], src + ksrc[i]);
                cp_commit();
            }

            const uint32_t slot = sb + SM_K + (c & 1) * SLOT2;
#pragma unroll
            for (int ks = 0; ks < 4; ks++) {
                const int kbase_a = c4 * 128 + ks * 32;  // Q: full-d rows
                const int kbase_b = ks * 32;             // K slot: 64-d rows
                uint32_t a[2][4];
                LDSM_X4(a[0][0], a[0][1], a[0][2], a[0][3], qlm + kbase_a);
                LDSM_X4(a[1][0], a[1][1], a[1][2], a[1][3],
                        qlm + 16 * QST + kbase_a);
#pragma unroll
                for (int nbp = 0; nbp < 4; nbp++) {
                    uint32_t b0, b1, c0, c1;
                    LDSM_X4(b0, b1, c0, c1,
                            slot + klm + nbp * 16 * KST2 + kbase_b);
                    MMA_BF16(S[0][2 * nbp],     a[0][0], a[0][1], a[0][2],
                             a[0][3], b0, b1);
                    MMA_BF16(S[0][2 * nbp + 1], a[0][0], a[0][1], a[0][2],
                             a[0][3], c0, c1);
                    MMA_BF16(S[1][2 * nbp],     a[1][0], a[1][1], a[1][2],
                             a[1][3], b0, b1);
                    MMA_BF16(S[1][2 * nbp + 1], a[1][0], a[1][1], a[1][2],
                             a[1][3], c0, c1);
                }
            }
        }

        // ---- epilogue: p = ex2(s*scale); PV via tensor pipe ----
        uint32_t vb[4][2];
#pragma unroll
        for (int kg = 0; kg < 4; kg++)
            LDSM_X2_TRANS(vb[kg][0], vb[kg][1], vlm + t * 2048 + kg * 256);
#pragma unroll
        for (int mt = 0; mt < 2; mt++)
#pragma unroll
            for (int nbp = 0; nbp < 4; nbp++) {
                float p0 = ex2f(S[mt][2 * nbp][0] * SCALE_EX2);
                float p1 = ex2f(S[mt][2 * nbp][1] * SCALE_EX2);
                float p2 = ex2f(S[mt][2 * nbp][2] * SCALE_EX2);
                float p3 = ex2f(S[mt][2 * nbp][3] * SCALE_EX2);
                float q0 = ex2f(S[mt][2 * nbp + 1][0] * SCALE_EX2);
                float q1 = ex2f(S[mt][2 * nbp + 1][1] * SCALE_EX2);
                float q2 = ex2f(S[mt][2 * nbp + 1][2] * SCALE_EX2);
                float q3 = ex2f(S[mt][2 * nbp + 1][3] * SCALE_EX2);
                uint32_t a0 = bf2(p0, p1), a1 = bf2(p2, p3);
                uint32_t a2 = bf2(q0, q1), a3 = bf2(q2, q3);
                MMA_BF16(O[mt], a0, a1, a2, a3, vb[nbp][0], vb[nbp][1]);
            }
    }

    // ---- extract (l, ax, ay) + cross-warpn reduction (red overlays K) ----
    float4* __restrict__ red = (float4*)(smem + SM_R);
    __syncthreads();                        // K-slot loads done before overlay
#pragma unroll
    for (int mt = 0; mt < 2; mt++)
#pragma unroll
        for (int half = 0; half < 2; half++) {
            float axv = O[mt][half * 2 + 0];
            float ayv = O[mt][half * 2 + 1];
            float lv  = __shfl_sync(0xffffffffu, O[mt][half * 2],
                                    (lane & 28) | 1);
            if (t4 == 0) {
                int rowl = warpm * 32 + mt * 16 + half * 8 + g;
                red[warpn * 128 + rowl] = make_float4(lv, axv, ayv, 0.f);
            }
        }
    __syncthreads();

    if (tid < 128) {
        float4 r0 = red[tid], r1 = red[128 + tid];
        g_part[split][b * L_ + q0 + tid] =
            make_float4(r0.x + r1.x, r0.y + r1.y, r0.z + r1.z, 0.f);
    }
    __threadfence();
    __syncthreads();
    if (tid == 0)
        s_last = atomicAdd(&g_cnt[b * 32 + blockIdx.x], 1);
    __syncthreads();

    // Last-arriving split CTA merges all partials and writes outputs.
    if (s_last == NSPLIT - 1 && tid < 128) {
        int i = b * L_ + q0 + tid;
        float lv = 0.f, axv = 0.f, ayv = 0.f;
#pragma unroll
        for (int sp = 0; sp < NSPLIT; sp++) {
            float4 p = g_part[sp][i];
            lv += p.x; axv += p.y; ayv += p.z;
        }
        float a = 1.0f / (1.0f + __expf(-alpha_p[0]));
        float inv = 1.0f / lv;
        float wx = axv * inv, wy = ayv * inv;
        float2 c = ((const float2*)coords)[i];
        float nx = a * wx + (1.0f - a) * c.x;
        float ny = a * wy + (1.0f - a) * c.y;
        out_new[2 * i + 0]  = nx;
        out_new[2 * i + 1]  = ny;
        out_disp[2 * i + 0] = nx - c.x;
        out_disp[2 * i + 1] = ny - c.y;
    }
}

// ---------------------------------------------------------------------------
// Inputs: latents, current_coords, Wq, Wk, alpha_raw, layer_idx.
// Output: concat(new_coords[B,L,2], displacement[B,L,2]) fp32.
// ---------------------------------------------------------------------------
extern "C" void kernel_launch(void* const* d_in, const int* in_sizes, int n_in,
                              void* d_out, int out_size) {
    const float* latents   = (const float*)d_in[0];
    const float* coords    = (const float*)d_in[1];
    const float* Wq        = (const float*)d_in[2];
    const float* Wk        = (const float*)d_in[3];
    const float* alpha_raw = (const float*)d_in[4];
    float* out = (float*)d_out;

    cudaFuncSetAttribute(proj_mma_kernel,
                         cudaFuncAttributeMaxDynamicSharedMemorySize, P_TOT);
    proj_mma_kernel<<<BL_ / 128, 512, P_TOT>>>(latents, Wq, Wk);

    cudaFuncSetAttribute(attn_kernel,
                         cudaFuncAttributeMaxDynamicSharedMemorySize, SM_TOT);
    attn_kernel<<<dim3(L_ / 128, B_, NSPLIT), 256, SM_TOT>>>(
        coords, alpha_raw, out, out + BL_ * 2);
}